// round 1
// baseline (speedup 1.0000x reference)
#include <cuda_runtime.h>
#include <cuda_bf16.h>
#include <math.h>

// ---------------------------------------------------------------------------
// Problem dims (fixed)
// ---------------------------------------------------------------------------
#define BATCH 8
#define CH    512         // Cin = Cout = S = 512
#define HI    32
#define WI    32
#define HO    64
#define WO    64
#define HP    66          // padded (HO+2)
#define WP    66
#define PLANE_P (HP*WP)   // 4356
#define PLANE_O (HO*WO)   // 4096
#define NPLANES (BATCH*CH)

// ---------------------------------------------------------------------------
// Scratch (static device memory — no allocations)
// ---------------------------------------------------------------------------
__device__ float g_xs_pad[(size_t)NPLANES * PLANE_P];   // modulated+upsampled x, zero-padded
__device__ float g_h1_pad[(size_t)NPLANES * PLANE_P];   // conv1 output (post act), zero-padded
__device__ float g_s1[BATCH * CH];
__device__ float g_s2[BATCH * CH];
__device__ float g_sr[BATCH * CH];
__device__ float g_d1[BATCH * CH];
__device__ float g_d2[BATCH * CH];
__device__ float g_wsq1[CH * CH];
__device__ float g_wsq2[CH * CH];

// ---------------------------------------------------------------------------
// styles: s[b,c] = sum_t w[b,t] * mod_w[c,t] + mod_b[c]
// ---------------------------------------------------------------------------
__global__ void style_kernel(const float* __restrict__ w,
                             const float* __restrict__ mw,
                             const float* __restrict__ mb,
                             float* __restrict__ sout)
{
    int idx = blockIdx.x * blockDim.x + threadIdx.x;      // 4096
    if (idx >= BATCH * CH) return;
    int b = idx >> 9;
    int c = idx & 511;
    const float* wb  = w  + (size_t)b * CH;
    const float* mwc = mw + (size_t)c * CH;
    float acc = mb[c];
    #pragma unroll 8
    for (int t = 0; t < CH; t++) acc += wb[t] * mwc[t];
    sout[idx] = acc;
}

// wsq[co,ci] = sum_tap W[co,ci,tap]^2
__global__ void wsq_kernel(const float* __restrict__ wgt, float* __restrict__ wsq)
{
    int idx = blockIdx.x * blockDim.x + threadIdx.x;      // 512*512
    if (idx >= CH * CH) return;
    const float* p = wgt + (size_t)idx * 9;
    float a = 0.f;
    #pragma unroll
    for (int t = 0; t < 9; t++) a += p[t] * p[t];
    wsq[idx] = a;
}

// d[b,co] = rsqrt( sum_ci wsq[co,ci]*s[b,ci]^2 + 1e-8 )
__global__ void demod_kernel(const float* __restrict__ wsq,
                             const float* __restrict__ s,
                             float* __restrict__ d)
{
    int idx = blockIdx.x * blockDim.x + threadIdx.x;      // 4096
    if (idx >= BATCH * CH) return;
    int b = idx >> 9;
    int co = idx & 511;
    const float* sb = s + (size_t)b * CH;
    const float* wr = wsq + (size_t)co * CH;
    float a = 0.f;
    #pragma unroll 8
    for (int ci = 0; ci < CH; ci++) {
        float sv = sb[ci];
        a += wr[ci] * sv * sv;
    }
    d[idx] = rsqrtf(a + 1e-8f);
}

// ---------------------------------------------------------------------------
// zero the 1-wide border of each padded plane
// ---------------------------------------------------------------------------
__global__ void zero_border_kernel(float* __restrict__ buf)
{
    int plane = blockIdx.x;        // NPLANES
    int t = threadIdx.x;           // blockDim = 288, 260 used
    if (t >= 260) return;
    float* p = buf + (size_t)plane * PLANE_P;
    int row, col;
    if (t < 66)       { row = 0;  col = t; }
    else if (t < 132) { row = 65; col = t - 66; }
    else {
        int j = t - 132;           // 0..127
        row = 1 + (j >> 1);
        col = (j & 1) ? 65 : 0;
    }
    p[row * WP + col] = 0.f;
}

// ---------------------------------------------------------------------------
// modulate (s1) + bilinear 2x upsample (half-pixel, edge-clamped) -> padded buf
// ---------------------------------------------------------------------------
__global__ void upsample_mod_kernel(const float* __restrict__ x,
                                    const float* __restrict__ s1)
{
    int idx = blockIdx.x * blockDim.x + threadIdx.x;      // 2^24
    int xq = idx & 63;
    int yq = (idx >> 6) & 63;
    int plane = idx >> 12;                                // b*512+ci
    if (plane >= NPLANES) return;

    float sy = yq * 0.5f - 0.25f;                         // (y+0.5)/2 - 0.5
    float sx = xq * 0.5f - 0.25f;
    int y0 = (int)floorf(sy);  float fy = sy - (float)y0;
    int x0 = (int)floorf(sx);  float fx = sx - (float)x0;
    int ya = max(y0, 0), yb = min(y0 + 1, HI - 1);
    int xa = max(x0, 0), xb = min(x0 + 1, WI - 1);

    const float* xp = x + (size_t)plane * (HI * WI);
    float v00 = xp[ya * WI + xa];
    float v01 = xp[ya * WI + xb];
    float v10 = xp[yb * WI + xa];
    float v11 = xp[yb * WI + xb];
    float v = (1.f - fy) * ((1.f - fx) * v00 + fx * v01)
            +        fy  * ((1.f - fx) * v10 + fx * v11);
    v *= s1[plane];
    g_xs_pad[(size_t)plane * PLANE_P + (size_t)(yq + 1) * WP + (xq + 1)] = v;
}

// ---------------------------------------------------------------------------
// tiled 3x3 conv, 512->512, on padded [B,512,66,66] input.
// grid (8 cout-tiles, 32 row-pairs, 8 batch), block 256.
// tile: 64 couts x (2 rows x 64 cols) pixels; per-thread 8 co x 4 px regs.
// epilogue: *demod + noise_scale*noise, leaky 0.2, write (padded or dense).
// ---------------------------------------------------------------------------
#define TCO 64
#define BK  8

template<bool WRITE_PAD>
__global__ __launch_bounds__(256, 2)
void conv3x3_kernel(const float* __restrict__ xpad,     // [B,512,66,66]
                    const float* __restrict__ in_scale, // [B,512] or nullptr
                    const float* __restrict__ wgt,      // [512,512,3,3]
                    const float* __restrict__ dmod,     // [B,512]
                    const float* __restrict__ nscale,   // [512]
                    const float* __restrict__ noise,    // [B,1,64,64]
                    float* __restrict__ out)
{
    __shared__ float w_s[BK][9][TCO];
    __shared__ float x_s[BK][4][WP];

    const int b   = blockIdx.z;
    const int co0 = blockIdx.x * TCO;
    const int y0  = blockIdx.y * 2;
    const int tid = threadIdx.x;
    const int tco = tid & 7;            // 0..7  -> co group
    const int tp  = tid >> 3;           // 0..31 -> pixel group
    const int r   = tp >> 4;            // 0..1  row within tile
    const int cc  = (tp & 15) << 2;     // 0..60 col start

    float acc[8][4] = {};

    const float* xbase = xpad + (size_t)b * CH * PLANE_P;
    const float* sbase = in_scale ? (in_scale + (size_t)b * CH) : nullptr;

    #pragma unroll 1
    for (int ci0 = 0; ci0 < CH; ci0 += BK) {
        __syncthreads();
        // load weights: [ci][tap][co]
        for (int i = tid; i < TCO * BK * 9; i += 256) {
            int co_i = i / (BK * 9);
            int rem  = i % (BK * 9);
            int ci_i = rem / 9;
            int tap  = rem % 9;
            w_s[ci_i][tap][co_i] =
                wgt[((size_t)(co0 + co_i) * CH + (ci0 + ci_i)) * 9 + tap];
        }
        // load input patch: [ci][4 rows][66 cols], rows y0..y0+3 (padded coords)
        for (int i = tid; i < BK * 4 * WP; i += 256) {
            int ci_i = i / (4 * WP);
            int rem  = i % (4 * WP);
            int rr   = rem / WP;
            int col  = rem % WP;
            float v = xbase[(size_t)(ci0 + ci_i) * PLANE_P + (size_t)(y0 + rr) * WP + col];
            if (sbase) v *= sbase[ci0 + ci_i];
            x_s[ci_i][rr][col] = v;
        }
        __syncthreads();

        #pragma unroll
        for (int ci = 0; ci < BK; ci++) {
            float xr[3][6];
            #pragma unroll
            for (int dy = 0; dy < 3; dy++)
                #pragma unroll
                for (int j = 0; j < 6; j++)
                    xr[dy][j] = x_s[ci][r + dy][cc + j];

            #pragma unroll
            for (int dy = 0; dy < 3; dy++) {
                #pragma unroll
                for (int dx = 0; dx < 3; dx++) {
                    const float4 wa = *(const float4*)&w_s[ci][dy * 3 + dx][tco * 8];
                    const float4 wb = *(const float4*)&w_s[ci][dy * 3 + dx][tco * 8 + 4];
                    float wv[8] = {wa.x, wa.y, wa.z, wa.w, wb.x, wb.y, wb.z, wb.w};
                    #pragma unroll
                    for (int i2 = 0; i2 < 8; i2++)
                        #pragma unroll
                        for (int p = 0; p < 4; p++)
                            acc[i2][p] += wv[i2] * xr[dy][dx + p];
                }
            }
        }
    }

    // epilogue
    const int y = y0 + r;
    const float* nz = noise + (size_t)b * PLANE_O + (size_t)y * WO;
    #pragma unroll
    for (int i2 = 0; i2 < 8; i2++) {
        int co = co0 + tco * 8 + i2;
        float d  = dmod[b * CH + co];
        float ns = nscale[co];
        #pragma unroll
        for (int p = 0; p < 4; p++) {
            int xx = cc + p;
            float v = acc[i2][p] * d + ns * nz[xx];
            v = (v >= 0.f) ? v : 0.2f * v;
            if (WRITE_PAD)
                out[((size_t)b * CH + co) * PLANE_P + (size_t)(y + 1) * WP + (xx + 1)] = v;
            else
                out[((size_t)b * CH + co) * PLANE_O + (size_t)y * WO + xx] = v;
        }
    }
}

// ---------------------------------------------------------------------------
// to-RGB 1x1 conv: rgb[b,c,pix] = sum_ci rgbw[c,ci]*sr[b,ci]*h[b,ci,pix]
// grid (16, 8), block 256
// ---------------------------------------------------------------------------
__global__ void rgb_kernel(const float* __restrict__ h,
                           const float* __restrict__ rgbw,
                           const float* __restrict__ sr,
                           float* __restrict__ rgb)
{
    __shared__ float weff[3 * CH];
    int b = blockIdx.y;
    for (int i = threadIdx.x; i < 3 * CH; i += 256) {
        int c = i / CH, ci = i % CH;
        weff[i] = rgbw[c * CH + ci] * sr[b * CH + ci];
    }
    __syncthreads();
    int pix = blockIdx.x * 256 + threadIdx.x;     // 0..4095
    const float* hb = h + (size_t)b * CH * PLANE_O + pix;
    float a0 = 0.f, a1 = 0.f, a2 = 0.f;
    #pragma unroll 4
    for (int ci = 0; ci < CH; ci++) {
        float hv = hb[(size_t)ci * PLANE_O];
        a0 += weff[ci] * hv;
        a1 += weff[CH + ci] * hv;
        a2 += weff[2 * CH + ci] * hv;
    }
    float* rb = rgb + (size_t)b * 3 * PLANE_O + pix;
    rb[0]           = a0;
    rb[PLANE_O]     = a1;
    rb[2 * PLANE_O] = a2;
}

// ---------------------------------------------------------------------------
// launch
// ---------------------------------------------------------------------------
extern "C" void kernel_launch(void* const* d_in, const int* in_sizes, int n_in,
                              void* d_out, int out_size)
{
    const float* x   = (const float*)d_in[0];
    const float* w   = (const float*)d_in[1];
    const float* w1  = (const float*)d_in[2];
    const float* m1w = (const float*)d_in[3];
    const float* m1b = (const float*)d_in[4];
    const float* ns1 = (const float*)d_in[5];
    const float* w2  = (const float*)d_in[6];
    const float* m2w = (const float*)d_in[7];
    const float* m2b = (const float*)d_in[8];
    const float* ns2 = (const float*)d_in[9];
    const float* wr  = (const float*)d_in[10];
    const float* mrw = (const float*)d_in[11];
    const float* mrb = (const float*)d_in[12];
    const float* n1  = (const float*)d_in[13];
    const float* n2  = (const float*)d_in[14];

    float* out     = (float*)d_out;
    float* h_out   = out;                                    // [8,512,64,64]
    float* rgb_out = out + (size_t)BATCH * CH * PLANE_O;     // [8,3,64,64]

    // symbol addresses for scratch
    float *p_xs, *p_h1, *p_s1, *p_s2, *p_sr, *p_d1, *p_d2, *p_q1, *p_q2;
    cudaGetSymbolAddress((void**)&p_xs, g_xs_pad);
    cudaGetSymbolAddress((void**)&p_h1, g_h1_pad);
    cudaGetSymbolAddress((void**)&p_s1, g_s1);
    cudaGetSymbolAddress((void**)&p_s2, g_s2);
    cudaGetSymbolAddress((void**)&p_sr, g_sr);
    cudaGetSymbolAddress((void**)&p_d1, g_d1);
    cudaGetSymbolAddress((void**)&p_d2, g_d2);
    cudaGetSymbolAddress((void**)&p_q1, g_wsq1);
    cudaGetSymbolAddress((void**)&p_q2, g_wsq2);

    // styles
    style_kernel<<<16, 256>>>(w, m1w, m1b, p_s1);
    style_kernel<<<16, 256>>>(w, m2w, m2b, p_s2);
    style_kernel<<<16, 256>>>(w, mrw, mrb, p_sr);

    // weight squared sums + demod factors
    wsq_kernel<<<1024, 256>>>(w1, p_q1);
    wsq_kernel<<<1024, 256>>>(w2, p_q2);
    demod_kernel<<<16, 256>>>(p_q1, p_s1, p_d1);
    demod_kernel<<<16, 256>>>(p_q2, p_s2, p_d2);

    // pad borders
    zero_border_kernel<<<NPLANES, 288>>>(p_xs);
    zero_border_kernel<<<NPLANES, 288>>>(p_h1);

    // modulate + upsample
    upsample_mod_kernel<<<(BATCH * CH * PLANE_O) / 256, 256>>>(x, p_s1);

    // conv1: xs_pad -> h1_pad (interior), demod d1 + noise1 + leaky
    {
        dim3 grid(CH / TCO, HO / 2, BATCH);
        conv3x3_kernel<true><<<grid, 256>>>(p_xs, nullptr, w1, p_d1, ns1, n1, p_h1);
    }
    // conv2: h1_pad (scaled by s2 on load) -> h_out, demod d2 + noise2 + leaky
    {
        dim3 grid(CH / TCO, HO / 2, BATCH);
        conv3x3_kernel<false><<<grid, 256>>>(p_h1, p_s2, w2, p_d2, ns2, n2, h_out);
    }
    // rgb 1x1
    {
        dim3 grid(PLANE_O / 256, BATCH);
        rgb_kernel<<<grid, 256>>>(h_out, wr, p_sr, rgb_out);
    }
    (void)in_sizes; (void)n_in; (void)out_size;
}

// round 3
// speedup vs baseline: 4.0464x; 4.0464x over previous
#include <cuda_runtime.h>
#include <cuda_bf16.h>
#include <math.h>
#include <stdint.h>

// ---------------------------------------------------------------------------
// Problem dims (fixed)
// ---------------------------------------------------------------------------
#define BATCH 8
#define CH    512
#define HI    32
#define WI    32
#define HO    64
#define WO    64
#define HP    66
#define WP    66
#define PLANE_O (HO*WO)          // 4096

// ---------------------------------------------------------------------------
// Static device scratch (no allocations allowed)
// ---------------------------------------------------------------------------
// Activations, channels-last padded NHWC bf16: [B, 66, 66, 512]
__device__ __nv_bfloat16 g_a1h[(size_t)BATCH*HP*WP*CH];
__device__ __nv_bfloat16 g_a1l[(size_t)BATCH*HP*WP*CH];
__device__ __nv_bfloat16 g_a2h[(size_t)BATCH*HP*WP*CH];
__device__ __nv_bfloat16 g_a2l[(size_t)BATCH*HP*WP*CH];
// Weights repacked: [18 (hi taps 0..8, lo taps 9..17)][cout 512][ci 512] bf16
__device__ __nv_bfloat16 g_w1p[18LL*CH*CH];
__device__ __nv_bfloat16 g_w2p[18LL*CH*CH];
// styles / demod
__device__ float g_s1[BATCH*CH];
__device__ float g_s2[BATCH*CH];
__device__ float g_sr[BATCH*CH];
__device__ float g_d1[BATCH*CH];
__device__ float g_d2[BATCH*CH];
__device__ float g_wsq1[CH*CH];
__device__ float g_wsq2[CH*CH];

// ---------------------------------------------------------------------------
// PTX helpers (sm_80-era features only: cp.async, ldmatrix, mma.sync)
// ---------------------------------------------------------------------------
__device__ __forceinline__ uint32_t smem_u32(const void* p) {
    uint32_t a;
    asm("{ .reg .u64 t; cvta.to.shared.u64 t, %1; cvt.u32.u64 %0, t; }"
        : "=r"(a) : "l"(p));
    return a;
}

#define CP_ASYNC16(dst, src) \
    asm volatile("cp.async.cg.shared.global [%0], [%1], 16;" \
        :: "r"(dst), "l"(src) : "memory")
#define CP_COMMIT() asm volatile("cp.async.commit_group;" ::: "memory")
#define CP_WAIT(N)  asm volatile("cp.async.wait_group %0;" :: "n"(N) : "memory")

__device__ __forceinline__ void ldsm_x4(uint32_t r[4], uint32_t addr) {
    asm volatile("ldmatrix.sync.aligned.m8n8.x4.shared.b16 {%0,%1,%2,%3}, [%4];"
        : "=r"(r[0]), "=r"(r[1]), "=r"(r[2]), "=r"(r[3]) : "r"(addr));
}

__device__ __forceinline__ void mma_bf16(float d[4], const uint32_t a[4],
                                         uint32_t b0, uint32_t b1) {
    asm volatile(
        "mma.sync.aligned.m16n8k16.row.col.f32.bf16.bf16.f32 "
        "{%0,%1,%2,%3}, {%4,%5,%6,%7}, {%8,%9}, {%0,%1,%2,%3};"
        : "+f"(d[0]), "+f"(d[1]), "+f"(d[2]), "+f"(d[3])
        : "r"(a[0]), "r"(a[1]), "r"(a[2]), "r"(a[3]), "r"(b0), "r"(b1));
}

// ---------------------------------------------------------------------------
// Prep kernels (fp32, identical math to verified R1)
// ---------------------------------------------------------------------------
__global__ void style_kernel(const float* __restrict__ w, const float* __restrict__ mw,
                             const float* __restrict__ mb, float* __restrict__ sout)
{
    int idx = blockIdx.x * blockDim.x + threadIdx.x;
    if (idx >= BATCH * CH) return;
    int b = idx >> 9, c = idx & 511;
    const float* wb = w + (size_t)b * CH;
    const float* mwc = mw + (size_t)c * CH;
    float acc = mb[c];
    #pragma unroll 8
    for (int t = 0; t < CH; t++) acc += wb[t] * mwc[t];
    sout[idx] = acc;
}

__global__ void wsq_kernel(const float* __restrict__ wgt, float* __restrict__ wsq)
{
    int idx = blockIdx.x * blockDim.x + threadIdx.x;
    if (idx >= CH * CH) return;
    const float* p = wgt + (size_t)idx * 9;
    float a = 0.f;
    #pragma unroll
    for (int t = 0; t < 9; t++) a += p[t] * p[t];
    wsq[idx] = a;
}

__global__ void demod_kernel(const float* __restrict__ wsq, const float* __restrict__ s,
                             float* __restrict__ d)
{
    int idx = blockIdx.x * blockDim.x + threadIdx.x;
    if (idx >= BATCH * CH) return;
    int b = idx >> 9, co = idx & 511;
    const float* sb = s + (size_t)b * CH;
    const float* wr = wsq + (size_t)co * CH;
    float a = 0.f;
    #pragma unroll 8
    for (int ci = 0; ci < CH; ci++) { float sv = sb[ci]; a += wr[ci] * sv * sv; }
    d[idx] = rsqrtf(a + 1e-8f);
}

// weights fp32 [co][ci][3][3] -> bf16 hi/lo K-major: out[tap][co][ci], out[9+tap][co][ci]
__global__ void wpack_kernel(const float* __restrict__ w, __nv_bfloat16* __restrict__ out)
{
    int idx = blockIdx.x * blockDim.x + threadIdx.x;
    if (idx >= CH * CH * 9) return;
    int ci = idx & 511, co = (idx >> 9) & 511, tap = idx >> 18;
    float v = w[((size_t)co * CH + ci) * 9 + tap];
    __nv_bfloat16 h = __float2bfloat16(v);
    out[(size_t)tap * (CH * CH) + (size_t)co * CH + ci] = h;
    out[(size_t)(9 + tap) * (CH * CH) + (size_t)co * CH + ci] =
        __float2bfloat16(v - __bfloat162float(h));
}

// zero borders (260 border pixels, 512 ci = 256 u32) of all 4 NHWC bf16 buffers
__global__ void border_zero_kernel()
{
    int idx = blockIdx.x * blockDim.x + threadIdx.x;   // 8*260*256
    if (idx >= BATCH * 260 * 256) return;
    int u = idx & 255;
    int pb = idx >> 8;
    int bp = pb % 260, b = pb / 260;
    int row, col;
    if (bp < 66)       { row = 0;  col = bp; }
    else if (bp < 132) { row = 65; col = bp - 66; }
    else { int j = bp - 132; row = 1 + (j >> 1); col = (j & 1) ? 65 : 0; }
    size_t off = (((size_t)(b * HP + row)) * WP + col) * CH;   // bf16 elems
    ((uint32_t*)(g_a1h + off))[u] = 0;
    ((uint32_t*)(g_a1l + off))[u] = 0;
    ((uint32_t*)(g_a2h + off))[u] = 0;
    ((uint32_t*)(g_a2l + off))[u] = 0;
}

// modulate(s1) + bilinear 2x upsample -> NHWC padded bf16 hi/lo
// grid (8 ci-chunks, 64 y, 8 b), block 256
__global__ void upsample_pack_kernel(const float* __restrict__ x,
                                     const float* __restrict__ s1)
{
    __shared__ float rows[64][2][33];
    int b = blockIdx.z, y = blockIdx.y, c0 = blockIdx.x * 64;
    float syf = y * 0.5f - 0.25f;
    int y0i = (int)floorf(syf);
    float fy = syf - (float)y0i;
    int ya = max(y0i, 0), yb = min(y0i + 1, HI - 1);
    for (int i = threadIdx.x; i < 64 * 2 * 32; i += 256) {
        int ci = i >> 6, r = (i >> 5) & 1, xx = i & 31;
        rows[ci][r][xx] = x[(((size_t)(b * CH + c0 + ci)) * HI + (r ? yb : ya)) * WI + xx];
    }
    __syncthreads();
    int px = threadIdx.x >> 2;
    int g  = (threadIdx.x & 3) * 16;
    float sxf = px * 0.5f - 0.25f;
    int x0i = (int)floorf(sxf);
    float fx = sxf - (float)x0i;
    int xa = max(x0i, 0), xb = min(x0i + 1, WI - 1);
    size_t obase = (((size_t)(b * HP + y + 1)) * WP + (px + 1)) * CH + c0 + g;
    #pragma unroll
    for (int j = 0; j < 16; j++) {
        int ci = g + j;
        float v0 = rows[ci][0][xa] * (1.f - fx) + rows[ci][0][xb] * fx;
        float v1 = rows[ci][1][xa] * (1.f - fx) + rows[ci][1][xb] * fx;
        float v = (v0 * (1.f - fy) + v1 * fy) * s1[b * CH + c0 + ci];
        __nv_bfloat16 h = __float2bfloat16(v);
        g_a1h[obase + j] = h;
        g_a1l[obase + j] = __float2bfloat16(v - __bfloat162float(h));
    }
}

// ---------------------------------------------------------------------------
// mma.sync implicit-GEMM conv3x3, bf16 hi/lo x3 split, fp32 accumulate.
// Block: 512 threads (16 warps, 8M x 2N). Tile: M=256 pixels, N=128 couts,
// BK=64 ci per stage; K loop = 9 taps x 8 ci-chunks = 72 iters, 2-stage cp.async.
// PHASE 1: epilogue (demod,noise,leaky)*s2 -> conv2 bf16 hi/lo NHWC input
// PHASE 2: epilogue demod,noise,leaky -> h_out fp32 NCHW
// ---------------------------------------------------------------------------
#define STAGE 98304   // Ah 32K | Al 32K | Bh 16K | Bl 16K
#define DSMEM (2*STAGE)

template<int PHASE>
__global__ void __launch_bounds__(512, 1)
conv_mma_kernel(const __nv_bfloat16* __restrict__ aHi,
                const __nv_bfloat16* __restrict__ aLo,
                const __nv_bfloat16* __restrict__ wp,
                const float* __restrict__ dmod,
                const float* __restrict__ nscale,
                const float* __restrict__ noise,
                const float* __restrict__ s2,
                __nv_bfloat16* __restrict__ out_hi,
                __nv_bfloat16* __restrict__ out_lo,
                float* __restrict__ h_out)
{
    extern __shared__ __align__(128) char dsm[];
    __shared__ float e_d[128], e_ns[128], e_s2[128];

    const int tid = threadIdx.x;
    const int lane = tid & 31;
    const int wid = tid >> 5;
    const int warp_m = wid & 7;       // 8 rows of 32 pixels
    const int warp_n = wid >> 3;      // 2 cols of 64 couts
    const int co0 = blockIdx.x * 128;
    const int y0  = blockIdx.y * 4;   // 4 image rows = 256 pixels
    const int b   = blockIdx.z;

    const uint32_t sb = smem_u32(dsm);

    for (int i = tid; i < 128; i += 512) {
        e_d[i]  = dmod[b * CH + co0 + i];
        e_ns[i] = nscale[co0 + i];
        e_s2[i] = (PHASE == 1) ? s2[b * CH + co0 + i] : 0.f;
    }

    float acc[2][8][4] = {};

    // -------- cp.async stage issue --------
    auto issue = [&](int it, int buf) {
        const int tap = it >> 3;            // 0..8  (dy*3+dx)
        const int ci0 = (it & 7) << 6;      // 0..448
        const int dy = tap / 3, dx = tap % 3;
        const uint32_t S = sb + buf * STAGE;
        // A hi/lo: 256 rows x 8 col16 each
        #pragma unroll
        for (int rep = 0; rep < 8; rep++) {
            int i = tid + rep * 512;        // 0..4095
            int op  = i >> 11;
            int c   = i & 2047;
            int row = c >> 3, col = c & 7;
            int py = y0 + (row >> 6) + dy;
            int px = (row & 63) + dx;
            const __nv_bfloat16* g = (op ? aLo : aHi)
                + ((((size_t)b * HP + py) * WP + px) << 9) + ci0 + (col << 3);
            uint32_t d = S + (op << 15) + row * 128 + ((col ^ (row & 7)) << 4);
            CP_ASYNC16(d, g);
        }
        // B hi/lo: 128 rows x 8 col16 each
        #pragma unroll
        for (int rep = 0; rep < 4; rep++) {
            int i = tid + rep * 512;        // 0..2047
            int op  = i >> 10;
            int c   = i & 1023;
            int row = c >> 3, col = c & 7;
            const __nv_bfloat16* g = wp
                + (((size_t)(op * 9 + tap) * CH + co0 + row) << 9) + ci0 + (col << 3);
            uint32_t d = S + 65536 + (op << 14) + row * 128 + ((col ^ (row & 7)) << 4);
            CP_ASYNC16(d, g);
        }
        CP_COMMIT();
    };

    issue(0, 0);

    for (int it = 0; it < 72; ++it) {
        if (it + 1 < 72) { issue(it + 1, (it + 1) & 1); CP_WAIT(1); }
        else             { CP_WAIT(0); }
        __syncthreads();

        const uint32_t S   = sb + (it & 1) * STAGE;
        const uint32_t SBh = S + 65536;

        #pragma unroll
        for (int ks = 0; ks < 4; ks++) {
            uint32_t ah[2][4], al[2][4], bh[4][4], bl[4][4];
            const int colA = ks * 2 + (lane >> 4);
            #pragma unroll
            for (int mt = 0; mt < 2; mt++) {
                int row = warp_m * 32 + mt * 16 + (lane & 15);
                uint32_t ad = S + row * 128 + ((colA ^ (row & 7)) << 4);
                ldsm_x4(ah[mt], ad);
                ldsm_x4(al[mt], ad + 32768);
            }
            #pragma unroll
            for (int nt = 0; nt < 4; nt++) {
                int row = warp_n * 64 + nt * 16 + (lane & 15);
                uint32_t bd = SBh + row * 128 + ((colA ^ (row & 7)) << 4);
                ldsm_x4(bh[nt], bd);
                ldsm_x4(bl[nt], bd + 16384);
            }
            #pragma unroll
            for (int mt = 0; mt < 2; mt++)
                #pragma unroll
                for (int nt = 0; nt < 4; nt++)
                    #pragma unroll
                    for (int hf = 0; hf < 2; hf++) {
                        float* d = acc[mt][nt * 2 + hf];
                        uint32_t b0 = bh[nt][hf], b1 = bh[nt][hf + 2];
                        mma_bf16(d, ah[mt], b0, b1);          // Ah*Bh
                        mma_bf16(d, al[mt], b0, b1);          // Al*Bh
                        mma_bf16(d, ah[mt], bl[nt][hf], bl[nt][hf + 2]); // Ah*Bl
                    }
        }
        __syncthreads();
    }

    // -------- epilogue --------
    #pragma unroll
    for (int mt = 0; mt < 2; mt++) {
        #pragma unroll
        for (int rr = 0; rr < 2; rr++) {
            int m = warp_m * 32 + mt * 16 + rr * 8 + (lane >> 2);
            int py = y0 + (m >> 6);
            int px = m & 63;
            float nz = noise[(size_t)b * PLANE_O + py * WO + px];
            #pragma unroll
            for (int nj = 0; nj < 8; nj++) {
                int nrel = warp_n * 64 + nj * 8 + (lane & 3) * 2;
                float v0 = acc[mt][nj][rr * 2 + 0] * e_d[nrel]     + e_ns[nrel]     * nz;
                float v1 = acc[mt][nj][rr * 2 + 1] * e_d[nrel + 1] + e_ns[nrel + 1] * nz;
                v0 = (v0 >= 0.f) ? v0 : 0.2f * v0;
                v1 = (v1 >= 0.f) ? v1 : 0.2f * v1;
                if (PHASE == 1) {
                    v0 *= e_s2[nrel];
                    v1 *= e_s2[nrel + 1];
                    __nv_bfloat16 h0 = __float2bfloat16(v0);
                    __nv_bfloat16 h1 = __float2bfloat16(v1);
                    __nv_bfloat16 l0 = __float2bfloat16(v0 - __bfloat162float(h0));
                    __nv_bfloat16 l1 = __float2bfloat16(v1 - __bfloat162float(h1));
                    size_t o = ((((size_t)b * HP + py + 1) * WP) + px + 1) * CH + co0 + nrel;
                    *(__nv_bfloat162*)(out_hi + o) = __halves2bfloat162(h0, h1);
                    *(__nv_bfloat162*)(out_lo + o) = __halves2bfloat162(l0, l1);
                } else {
                    size_t o = ((size_t)b * CH + co0 + nrel) * PLANE_O + py * WO + px;
                    h_out[o] = v0;
                    h_out[o + PLANE_O] = v1;
                }
            }
        }
    }
}

// ---------------------------------------------------------------------------
// to-RGB 1x1 conv
// ---------------------------------------------------------------------------
__global__ void rgb_kernel(const float* __restrict__ h, const float* __restrict__ rgbw,
                           const float* __restrict__ sr, float* __restrict__ rgb)
{
    __shared__ float weff[3 * CH];
    int b = blockIdx.y;
    for (int i = threadIdx.x; i < 3 * CH; i += 256) {
        int c = i / CH, ci = i % CH;
        weff[i] = rgbw[c * CH + ci] * sr[b * CH + ci];
    }
    __syncthreads();
    int pix = blockIdx.x * 256 + threadIdx.x;
    const float* hb = h + (size_t)b * CH * PLANE_O + pix;
    float a0 = 0.f, a1 = 0.f, a2 = 0.f;
    #pragma unroll 4
    for (int ci = 0; ci < CH; ci++) {
        float hv = hb[(size_t)ci * PLANE_O];
        a0 += weff[ci] * hv;
        a1 += weff[CH + ci] * hv;
        a2 += weff[2 * CH + ci] * hv;
    }
    float* rb = rgb + (size_t)b * 3 * PLANE_O + pix;
    rb[0] = a0; rb[PLANE_O] = a1; rb[2 * PLANE_O] = a2;
}

// ---------------------------------------------------------------------------
// host launch
// ---------------------------------------------------------------------------
extern "C" void kernel_launch(void* const* d_in, const int* in_sizes, int n_in,
                              void* d_out, int out_size)
{
    const float* x   = (const float*)d_in[0];
    const float* w   = (const float*)d_in[1];
    const float* w1  = (const float*)d_in[2];
    const float* m1w = (const float*)d_in[3];
    const float* m1b = (const float*)d_in[4];
    const float* ns1 = (const float*)d_in[5];
    const float* w2  = (const float*)d_in[6];
    const float* m2w = (const float*)d_in[7];
    const float* m2b = (const float*)d_in[8];
    const float* ns2 = (const float*)d_in[9];
    const float* wr  = (const float*)d_in[10];
    const float* mrw = (const float*)d_in[11];
    const float* mrb = (const float*)d_in[12];
    const float* n1  = (const float*)d_in[13];
    const float* n2  = (const float*)d_in[14];

    float* out     = (float*)d_out;
    float* h_out   = out;                                  // [8,512,64,64]
    float* rgb_out = out + (size_t)BATCH * CH * PLANE_O;   // [8,3,64,64]

    float *p_s1, *p_s2, *p_sr, *p_d1, *p_d2, *p_q1, *p_q2;
    __nv_bfloat16 *p_a1h, *p_a1l, *p_a2h, *p_a2l, *p_w1p, *p_w2p;
    cudaGetSymbolAddress((void**)&p_s1, g_s1);
    cudaGetSymbolAddress((void**)&p_s2, g_s2);
    cudaGetSymbolAddress((void**)&p_sr, g_sr);
    cudaGetSymbolAddress((void**)&p_d1, g_d1);
    cudaGetSymbolAddress((void**)&p_d2, g_d2);
    cudaGetSymbolAddress((void**)&p_q1, g_wsq1);
    cudaGetSymbolAddress((void**)&p_q2, g_wsq2);
    cudaGetSymbolAddress((void**)&p_a1h, g_a1h);
    cudaGetSymbolAddress((void**)&p_a1l, g_a1l);
    cudaGetSymbolAddress((void**)&p_a2h, g_a2h);
    cudaGetSymbolAddress((void**)&p_a2l, g_a2l);
    cudaGetSymbolAddress((void**)&p_w1p, g_w1p);
    cudaGetSymbolAddress((void**)&p_w2p, g_w2p);

    cudaFuncSetAttribute(conv_mma_kernel<1>, cudaFuncAttributeMaxDynamicSharedMemorySize, DSMEM);
    cudaFuncSetAttribute(conv_mma_kernel<2>, cudaFuncAttributeMaxDynamicSharedMemorySize, DSMEM);

    // prep
    style_kernel<<<16, 256>>>(w, m1w, m1b, p_s1);
    style_kernel<<<16, 256>>>(w, m2w, m2b, p_s2);
    style_kernel<<<16, 256>>>(w, mrw, mrb, p_sr);
    wsq_kernel<<<1024, 256>>>(w1, p_q1);
    wsq_kernel<<<1024, 256>>>(w2, p_q2);
    demod_kernel<<<16, 256>>>(p_q1, p_s1, p_d1);
    demod_kernel<<<16, 256>>>(p_q2, p_s2, p_d2);
    wpack_kernel<<<(CH * CH * 9 + 255) / 256, 256>>>(w1, p_w1p);
    wpack_kernel<<<(CH * CH * 9 + 255) / 256, 256>>>(w2, p_w2p);
    border_zero_kernel<<<(BATCH * 260 * 256 + 255) / 256, 256>>>();
    {
        dim3 g(8, 64, 8);
        upsample_pack_kernel<<<g, 256>>>(x, p_s1);
    }
    // conv1 (reads a1 hi/lo, writes conv2 input a2 hi/lo, modulated by s2)
    {
        dim3 g(4, 16, 8);
        conv_mma_kernel<1><<<g, 512, DSMEM>>>(p_a1h, p_a1l, p_w1p, p_d1, ns1, n1,
                                              p_s2, p_a2h, p_a2l, nullptr);
    }
    // conv2 (reads a2 hi/lo, writes h_out fp32)
    {
        dim3 g(4, 16, 8);
        conv_mma_kernel<2><<<g, 512, DSMEM>>>(p_a2h, p_a2l, p_w2p, p_d2, ns2, n2,
                                              nullptr, nullptr, nullptr, h_out);
    }
    // rgb
    {
        dim3 g(PLANE_O / 256, BATCH);
        rgb_kernel<<<g, 256>>>(h_out, wr, p_sr, rgb_out);
    }
    (void)in_sizes; (void)n_in; (void)out_size;
}

// round 4
// speedup vs baseline: 4.2429x; 1.0486x over previous
#include <cuda_runtime.h>
#include <cuda_bf16.h>
#include <math.h>
#include <stdint.h>

// ---------------------------------------------------------------------------
// Problem dims (fixed)
// ---------------------------------------------------------------------------
#define BATCH 8
#define CH    512
#define HI    32
#define WI    32
#define HO    64
#define WO    64
#define HP    66
#define WP    66
#define PLANE_O (HO*WO)          // 4096

// ---------------------------------------------------------------------------
// Static device scratch (no allocations allowed)
// ---------------------------------------------------------------------------
__device__ __nv_bfloat16 g_a1h[(size_t)BATCH*HP*WP*CH];
__device__ __nv_bfloat16 g_a1l[(size_t)BATCH*HP*WP*CH];
__device__ __nv_bfloat16 g_a2h[(size_t)BATCH*HP*WP*CH];
__device__ __nv_bfloat16 g_a2l[(size_t)BATCH*HP*WP*CH];
// Weights repacked: [18 (hi taps 0..8, lo taps 9..17)][cout 512][ci 512] bf16
__device__ __nv_bfloat16 g_w1p[18LL*CH*CH];
__device__ __nv_bfloat16 g_w2p[18LL*CH*CH];
__device__ float g_s1[BATCH*CH];
__device__ float g_s2[BATCH*CH];
__device__ float g_sr[BATCH*CH];
__device__ float g_d1[BATCH*CH];
__device__ float g_d2[BATCH*CH];

// ---------------------------------------------------------------------------
// PTX helpers (base-target features only: cp.async, ldmatrix, mma.sync)
// ---------------------------------------------------------------------------
__device__ __forceinline__ uint32_t smem_u32(const void* p) {
    uint32_t a;
    asm("{ .reg .u64 t; cvta.to.shared.u64 t, %1; cvt.u32.u64 %0, t; }"
        : "=r"(a) : "l"(p));
    return a;
}

#define CP_ASYNC16(dst, src) \
    asm volatile("cp.async.cg.shared.global [%0], [%1], 16;" \
        :: "r"(dst), "l"(src) : "memory")
#define CP_COMMIT() asm volatile("cp.async.commit_group;" ::: "memory")
#define CP_WAIT(N)  asm volatile("cp.async.wait_group %0;" :: "n"(N) : "memory")

__device__ __forceinline__ void ldsm_x4(uint32_t r[4], uint32_t addr) {
    asm volatile("ldmatrix.sync.aligned.m8n8.x4.shared.b16 {%0,%1,%2,%3}, [%4];"
        : "=r"(r[0]), "=r"(r[1]), "=r"(r[2]), "=r"(r[3]) : "r"(addr));
}

__device__ __forceinline__ void mma_bf16(float d[4], const uint32_t a[4],
                                         uint32_t b0, uint32_t b1) {
    asm volatile(
        "mma.sync.aligned.m16n8k16.row.col.f32.bf16.bf16.f32 "
        "{%0,%1,%2,%3}, {%4,%5,%6,%7}, {%8,%9}, {%0,%1,%2,%3};"
        : "+f"(d[0]), "+f"(d[1]), "+f"(d[2]), "+f"(d[3])
        : "r"(a[0]), "r"(a[1]), "r"(a[2]), "r"(a[3]), "r"(b0), "r"(b1));
}

// ---------------------------------------------------------------------------
// 1) styles for all three mod layers in one launch. grid 48 x 256
// ---------------------------------------------------------------------------
__global__ void style_all_kernel(const float* __restrict__ w,
                                 const float* __restrict__ m1w, const float* __restrict__ m1b,
                                 const float* __restrict__ m2w, const float* __restrict__ m2b,
                                 const float* __restrict__ mrw, const float* __restrict__ mrb)
{
    int idx = blockIdx.x * 256 + threadIdx.x;    // 0 .. 3*4096
    if (idx >= 3 * BATCH * CH) return;
    int sel = idx >> 12;
    int r = idx & 4095;
    const float* mw = (sel == 0) ? m1w : (sel == 1) ? m2w : mrw;
    const float* mb = (sel == 0) ? m1b : (sel == 1) ? m2b : mrb;
    float* outp = (sel == 0) ? g_s1 : (sel == 1) ? g_s2 : g_sr;
    int b = r >> 9, c = r & 511;
    const float* wb = w + (size_t)b * CH;
    const float* mwc = mw + (size_t)c * CH;
    float acc = mb[c];
    #pragma unroll 8
    for (int t = 0; t < CH; t++) acc += wb[t] * mwc[t];
    outp[r] = acc;
}

// ---------------------------------------------------------------------------
// 2) demod directly from weights: one block per (which, b, co), block-reduce.
//    d[b,co] = rsqrt( sum_ci (sum_tap w^2) * s[b,ci]^2 + 1e-8 )
// ---------------------------------------------------------------------------
__global__ void demod_direct_kernel(const float* __restrict__ w1,
                                    const float* __restrict__ w2)
{
    __shared__ float red[256];
    const int which = blockIdx.y;
    const float* wgt = which ? w2 : w1;
    const float* s   = which ? g_s2 : g_s1;
    float* d         = which ? g_d2 : g_d1;
    const int b  = blockIdx.x >> 9;
    const int co = blockIdx.x & 511;
    const int t  = threadIdx.x;

    float partial = 0.f;
    #pragma unroll
    for (int h = 0; h < 2; h++) {
        int ci = t + h * 256;
        const float* p = wgt + ((size_t)co * CH + ci) * 9;
        float a = 0.f;
        #pragma unroll
        for (int tap = 0; tap < 9; tap++) a += p[tap] * p[tap];
        float sv = s[b * CH + ci];
        partial += a * sv * sv;
    }
    red[t] = partial;
    __syncthreads();
    for (int off = 128; off >= 32; off >>= 1) {
        if (t < off) red[t] += red[t + off];
        __syncthreads();
    }
    if (t < 32) {
        float v = red[t];
        #pragma unroll
        for (int off = 16; off > 0; off >>= 1)
            v += __shfl_down_sync(0xffffffffu, v, off);
        if (t == 0) d[b * CH + co] = rsqrtf(v + 1e-8f);
    }
}

// ---------------------------------------------------------------------------
// 3) weights fp32 [co][ci][3][3] -> bf16 hi/lo K-major [tap][co][ci]; z picks conv
// ---------------------------------------------------------------------------
__global__ void wpack_all_kernel(const float* __restrict__ w1, const float* __restrict__ w2)
{
    int idx = blockIdx.x * blockDim.x + threadIdx.x;
    if (idx >= CH * CH * 9) return;
    const float* w = blockIdx.y ? w2 : w1;
    __nv_bfloat16* out = blockIdx.y ? g_w2p : g_w1p;
    int ci = idx & 511, co = (idx >> 9) & 511, tap = idx >> 18;
    float v = w[((size_t)co * CH + ci) * 9 + tap];
    __nv_bfloat16 h = __float2bfloat16(v);
    out[(size_t)tap * (CH * CH) + (size_t)co * CH + ci] = h;
    out[(size_t)(9 + tap) * (CH * CH) + (size_t)co * CH + ci] =
        __float2bfloat16(v - __bfloat162float(h));
}

// ---------------------------------------------------------------------------
// 4) modulate(s1) + bilinear 2x upsample -> NHWC padded bf16 hi/lo,
//    plus border zeroing of all 4 activation buffers (y==64 branch).
//    grid (8, 65, 8), block 256
// ---------------------------------------------------------------------------
__global__ void upsample_pack_kernel(const float* __restrict__ x)
{
    __shared__ float rows[64][2][33];
    int b = blockIdx.z, y = blockIdx.y, c0 = blockIdx.x * 64;

    if (y == 64) {
        // border zero: 260 border pixels x 256 u32 (512 bf16 ch) per buffer
        for (int i = blockIdx.x * 256 + threadIdx.x; i < 260 * 256; i += 8 * 256) {
            int u = i & 255;
            int bp = i >> 8;
            int row, col;
            if (bp < 66)       { row = 0;  col = bp; }
            else if (bp < 132) { row = 65; col = bp - 66; }
            else { int j = bp - 132; row = 1 + (j >> 1); col = (j & 1) ? 65 : 0; }
            size_t off = (((size_t)(b * HP + row)) * WP + col) * CH;
            ((uint32_t*)(g_a1h + off))[u] = 0;
            ((uint32_t*)(g_a1l + off))[u] = 0;
            ((uint32_t*)(g_a2h + off))[u] = 0;
            ((uint32_t*)(g_a2l + off))[u] = 0;
        }
        return;
    }

    float syf = y * 0.5f - 0.25f;
    int y0i = (int)floorf(syf);
    float fy = syf - (float)y0i;
    int ya = max(y0i, 0), yb = min(y0i + 1, HI - 1);
    for (int i = threadIdx.x; i < 64 * 2 * 32; i += 256) {
        int ci = i >> 6, r = (i >> 5) & 1, xx = i & 31;
        rows[ci][r][xx] = x[(((size_t)(b * CH + c0 + ci)) * HI + (r ? yb : ya)) * WI + xx];
    }
    __syncthreads();
    int px = threadIdx.x >> 2;
    int g  = (threadIdx.x & 3) * 16;
    float sxf = px * 0.5f - 0.25f;
    int x0i = (int)floorf(sxf);
    float fx = sxf - (float)x0i;
    int xa = max(x0i, 0), xb = min(x0i + 1, WI - 1);
    size_t obase = (((size_t)(b * HP + y + 1)) * WP + (px + 1)) * CH + c0 + g;
    #pragma unroll
    for (int j = 0; j < 16; j++) {
        int ci = g + j;
        float v0 = rows[ci][0][xa] * (1.f - fx) + rows[ci][0][xb] * fx;
        float v1 = rows[ci][1][xa] * (1.f - fx) + rows[ci][1][xb] * fx;
        float v = (v0 * (1.f - fy) + v1 * fy) * g_s1[b * CH + c0 + ci];
        __nv_bfloat16 h = __float2bfloat16(v);
        g_a1h[obase + j] = h;
        g_a1l[obase + j] = __float2bfloat16(v - __bfloat162float(h));
    }
}

// ---------------------------------------------------------------------------
// mma.sync implicit-GEMM conv3x3, bf16 hi/lo x3 split, fp32 accumulate.
// Block: 256 threads (8 warps, 2M x 4N). Tile: M=128 pixels, N=256 couts,
// BK=64 ci/stage; K loop = 9 taps x 8 ci-chunks = 72 iters, 2-stage cp.async.
// Warp tile 64x64 (acc 128 regs). No spills at 256 thr (256 regs avail).
// PHASE 1: epilogue (demod,noise,leaky)*s2 -> conv2 bf16 hi/lo NHWC input
// PHASE 2: epilogue demod,noise,leaky -> h_out fp32 NCHW
// ---------------------------------------------------------------------------
#define STAGE 98304   // Ah 16K | Al 16K | Bh 32K | Bl 32K
#define DSMEM (2*STAGE)

template<int PHASE>
__global__ void __launch_bounds__(256, 1)
conv_mma_kernel(const __nv_bfloat16* __restrict__ aHi,
                const __nv_bfloat16* __restrict__ aLo,
                const __nv_bfloat16* __restrict__ wp,
                const float* __restrict__ dmod,
                const float* __restrict__ nscale,
                const float* __restrict__ noise,
                const float* __restrict__ s2,
                __nv_bfloat16* __restrict__ out_hi,
                __nv_bfloat16* __restrict__ out_lo,
                float* __restrict__ h_out)
{
    extern __shared__ __align__(128) char dsm[];
    __shared__ float e_d[256], e_ns[256], e_s2[256];

    const int tid = threadIdx.x;
    const int lane = tid & 31;
    const int wid = tid >> 5;
    const int warp_m = wid & 1;       // 2 x 64 pixels
    const int warp_n = wid >> 1;      // 4 x 64 couts
    const int co0 = blockIdx.x * 256;
    const int y0  = blockIdx.y * 2;   // 2 image rows = 128 pixels
    const int b   = blockIdx.z;

    const uint32_t sb = smem_u32(dsm);

    for (int i = tid; i < 256; i += 256) {
        e_d[i]  = dmod[b * CH + co0 + i];
        e_ns[i] = nscale[co0 + i];
        e_s2[i] = (PHASE == 1) ? s2[b * CH + co0 + i] : 0.f;
    }

    float acc[4][8][4] = {};

    // -------- cp.async stage issue --------
    auto issue = [&](int it, int buf) {
        const int tap = it >> 3;            // dy*3+dx
        const int ci0 = (it & 7) << 6;
        const int dy = tap / 3, dx = tap % 3;
        const uint32_t S = sb + buf * STAGE;
        // A hi/lo: 128 rows x 8 col16 x 2 ops = 2048 chunks, 8 per thread
        #pragma unroll
        for (int rep = 0; rep < 8; rep++) {
            int i = tid + rep * 256;
            int op  = i >> 10;
            int c   = i & 1023;
            int row = c >> 3, col = c & 7;
            int py = y0 + (row >> 6) + dy;
            int px = (row & 63) + dx;
            const __nv_bfloat16* g = (op ? aLo : aHi)
                + ((((size_t)b * HP + py) * WP + px) << 9) + ci0 + (col << 3);
            uint32_t d = S + (op << 14) + row * 128 + ((col ^ (row & 7)) << 4);
            CP_ASYNC16(d, g);
        }
        // B hi/lo: 256 rows x 8 col16 x 2 ops = 4096 chunks, 16 per thread
        #pragma unroll
        for (int rep = 0; rep < 16; rep++) {
            int i = tid + rep * 256;
            int op  = i >> 11;
            int c   = i & 2047;
            int row = c >> 3, col = c & 7;
            const __nv_bfloat16* g = wp
                + (((size_t)(op * 9 + tap) * CH + co0 + row) << 9) + ci0 + (col << 3);
            uint32_t d = S + 32768 + (op << 15) + row * 128 + ((col ^ (row & 7)) << 4);
            CP_ASYNC16(d, g);
        }
        CP_COMMIT();
    };

    issue(0, 0);

    #pragma unroll 1
    for (int it = 0; it < 72; ++it) {
        if (it + 1 < 72) { issue(it + 1, (it + 1) & 1); CP_WAIT(1); }
        else             { CP_WAIT(0); }
        __syncthreads();

        const uint32_t S = sb + (it & 1) * STAGE;

        #pragma unroll
        for (int ks = 0; ks < 4; ks++) {
            const int colA = ks * 2 + (lane >> 4);
            uint32_t ah[4][4], al[4][4], bh[4][4], bl[4][4];
            #pragma unroll
            for (int mt = 0; mt < 4; mt++) {
                int row = warp_m * 64 + mt * 16 + (lane & 15);
                uint32_t ad = S + row * 128 + ((colA ^ (row & 7)) << 4);
                ldsm_x4(ah[mt], ad);
                ldsm_x4(al[mt], ad + 16384);
            }
            #pragma unroll
            for (int nt = 0; nt < 4; nt++) {
                int row = warp_n * 64 + nt * 16 + (lane & 15);
                uint32_t bd = S + 32768 + row * 128 + ((colA ^ (row & 7)) << 4);
                ldsm_x4(bh[nt], bd);
                ldsm_x4(bl[nt], bd + 32768);
            }
            #pragma unroll
            for (int mt = 0; mt < 4; mt++)
                #pragma unroll
                for (int nt = 0; nt < 4; nt++)
                    #pragma unroll
                    for (int hf = 0; hf < 2; hf++) {
                        float* d = acc[mt][nt * 2 + hf];
                        uint32_t b0 = bh[nt][hf], b1 = bh[nt][hf + 2];
                        mma_bf16(d, ah[mt], b0, b1);                       // Ah*Bh
                        mma_bf16(d, al[mt], b0, b1);                       // Al*Bh
                        mma_bf16(d, ah[mt], bl[nt][hf], bl[nt][hf + 2]);   // Ah*Bl
                    }
        }
        __syncthreads();
    }

    // -------- epilogue --------
    #pragma unroll
    for (int mt = 0; mt < 4; mt++) {
        #pragma unroll
        for (int rr = 0; rr < 2; rr++) {
            int m = warp_m * 64 + mt * 16 + rr * 8 + (lane >> 2);
            int py = y0 + (m >> 6);
            int px = m & 63;
            float nz = noise[(size_t)b * PLANE_O + py * WO + px];
            #pragma unroll
            for (int nj = 0; nj < 8; nj++) {
                int nrel = warp_n * 64 + nj * 8 + (lane & 3) * 2;
                float v0 = acc[mt][nj][rr * 2 + 0] * e_d[nrel]     + e_ns[nrel]     * nz;
                float v1 = acc[mt][nj][rr * 2 + 1] * e_d[nrel + 1] + e_ns[nrel + 1] * nz;
                v0 = (v0 >= 0.f) ? v0 : 0.2f * v0;
                v1 = (v1 >= 0.f) ? v1 : 0.2f * v1;
                if (PHASE == 1) {
                    v0 *= e_s2[nrel];
                    v1 *= e_s2[nrel + 1];
                    __nv_bfloat16 h0 = __float2bfloat16(v0);
                    __nv_bfloat16 h1 = __float2bfloat16(v1);
                    __nv_bfloat16 l0 = __float2bfloat16(v0 - __bfloat162float(h0));
                    __nv_bfloat16 l1 = __float2bfloat16(v1 - __bfloat162float(h1));
                    size_t o = ((((size_t)b * HP + py + 1) * WP) + px + 1) * CH + co0 + nrel;
                    *(__nv_bfloat162*)(out_hi + o) = __halves2bfloat162(h0, h1);
                    *(__nv_bfloat162*)(out_lo + o) = __halves2bfloat162(l0, l1);
                } else {
                    size_t o = ((size_t)b * CH + co0 + nrel) * PLANE_O + py * WO + px;
                    h_out[o] = v0;
                    h_out[o + PLANE_O] = v1;
                }
            }
        }
    }
}

// ---------------------------------------------------------------------------
// to-RGB 1x1 conv
// ---------------------------------------------------------------------------
__global__ void rgb_kernel(const float* __restrict__ h, const float* __restrict__ rgbw,
                           float* __restrict__ rgb)
{
    __shared__ float weff[3 * CH];
    int b = blockIdx.y;
    for (int i = threadIdx.x; i < 3 * CH; i += 256) {
        int c = i / CH, ci = i % CH;
        weff[i] = rgbw[c * CH + ci] * g_sr[b * CH + ci];
    }
    __syncthreads();
    int pix = blockIdx.x * 256 + threadIdx.x;
    const float* hb = h + (size_t)b * CH * PLANE_O + pix;
    float a0 = 0.f, a1 = 0.f, a2 = 0.f;
    #pragma unroll 4
    for (int ci = 0; ci < CH; ci++) {
        float hv = hb[(size_t)ci * PLANE_O];
        a0 += weff[ci] * hv;
        a1 += weff[CH + ci] * hv;
        a2 += weff[2 * CH + ci] * hv;
    }
    float* rb = rgb + (size_t)b * 3 * PLANE_O + pix;
    rb[0] = a0; rb[PLANE_O] = a1; rb[2 * PLANE_O] = a2;
}

// ---------------------------------------------------------------------------
// host launch
// ---------------------------------------------------------------------------
extern "C" void kernel_launch(void* const* d_in, const int* in_sizes, int n_in,
                              void* d_out, int out_size)
{
    const float* x   = (const float*)d_in[0];
    const float* w   = (const float*)d_in[1];
    const float* w1  = (const float*)d_in[2];
    const float* m1w = (const float*)d_in[3];
    const float* m1b = (const float*)d_in[4];
    const float* ns1 = (const float*)d_in[5];
    const float* w2  = (const float*)d_in[6];
    const float* m2w = (const float*)d_in[7];
    const float* m2b = (const float*)d_in[8];
    const float* ns2 = (const float*)d_in[9];
    const float* wr  = (const float*)d_in[10];
    const float* n1  = (const float*)d_in[13];
    const float* n2  = (const float*)d_in[14];

    float* out     = (float*)d_out;
    float* h_out   = out;                                  // [8,512,64,64]
    float* rgb_out = out + (size_t)BATCH * CH * PLANE_O;   // [8,3,64,64]

    float *p_s2, *p_d1, *p_d2;
    __nv_bfloat16 *p_a1h, *p_a1l, *p_a2h, *p_a2l, *p_w1p, *p_w2p;
    cudaGetSymbolAddress((void**)&p_s2, g_s2);
    cudaGetSymbolAddress((void**)&p_d1, g_d1);
    cudaGetSymbolAddress((void**)&p_d2, g_d2);
    cudaGetSymbolAddress((void**)&p_a1h, g_a1h);
    cudaGetSymbolAddress((void**)&p_a1l, g_a1l);
    cudaGetSymbolAddress((void**)&p_a2h, g_a2h);
    cudaGetSymbolAddress((void**)&p_a2l, g_a2l);
    cudaGetSymbolAddress((void**)&p_w1p, g_w1p);
    cudaGetSymbolAddress((void**)&p_w2p, g_w2p);

    cudaFuncSetAttribute(conv_mma_kernel<1>, cudaFuncAttributeMaxDynamicSharedMemorySize, DSMEM);
    cudaFuncSetAttribute(conv_mma_kernel<2>, cudaFuncAttributeMaxDynamicSharedMemorySize, DSMEM);

    // 1. styles (all three)
    style_all_kernel<<<48, 256>>>(w, m1w, m1b, m2w, m2b, wr ? (const float*)d_in[11] : nullptr,
                                  (const float*)d_in[12]);
    // 2. demod factors (both convs), directly from weights
    {
        dim3 g(BATCH * CH, 2);
        demod_direct_kernel<<<g, 256>>>(w1, w2);
    }
    // 3. weight repack (both convs)
    {
        dim3 g((CH * CH * 9 + 255) / 256, 2);
        wpack_all_kernel<<<g, 256>>>(w1, w2);
    }
    // 4. modulate + upsample + border zero
    {
        dim3 g(8, 65, 8);
        upsample_pack_kernel<<<g, 256>>>(x);
    }
    // 5. conv1 (reads a1 hi/lo, writes conv2 input a2 hi/lo, pre-modulated by s2)
    {
        dim3 g(2, 32, 8);
        conv_mma_kernel<1><<<g, 256, DSMEM>>>(p_a1h, p_a1l, p_w1p, p_d1, ns1, n1,
                                              p_s2, p_a2h, p_a2l, nullptr);
    }
    // 6. conv2 (reads a2 hi/lo, writes h_out fp32)
    {
        dim3 g(2, 32, 8);
        conv_mma_kernel<2><<<g, 256, DSMEM>>>(p_a2h, p_a2l, p_w2p, p_d2, ns2, n2,
                                              nullptr, nullptr, nullptr, h_out);
    }
    // 7. rgb
    {
        dim3 g(PLANE_O / 256, BATCH);
        rgb_kernel<<<g, 256>>>(h_out, wr, rgb_out);
    }
    (void)in_sizes; (void)n_in; (void)out_size;
}

// round 6
// speedup vs baseline: 4.3828x; 1.0330x over previous
#include <cuda_runtime.h>
#include <cuda_bf16.h>
#include <math.h>
#include <stdint.h>

// ---------------------------------------------------------------------------
// Problem dims (fixed)
// ---------------------------------------------------------------------------
#define BATCH 8
#define CH    512
#define HI    32
#define WI    32
#define HO    64
#define WO    64
#define HP    66
#define WP    66
#define PLANE_O (HO*WO)          // 4096

// ---------------------------------------------------------------------------
// Static device scratch (no allocations allowed)
// ---------------------------------------------------------------------------
__device__ __nv_bfloat16 g_a1h[(size_t)BATCH*HP*WP*CH];
__device__ __nv_bfloat16 g_a1l[(size_t)BATCH*HP*WP*CH];
__device__ __nv_bfloat16 g_a2h[(size_t)BATCH*HP*WP*CH];
__device__ __nv_bfloat16 g_a2l[(size_t)BATCH*HP*WP*CH];
// Weights repacked: [18 (hi taps 0..8, lo taps 9..17)][cout 512][ci 512] bf16
__device__ __nv_bfloat16 g_w1p[18LL*CH*CH];
__device__ __nv_bfloat16 g_w2p[18LL*CH*CH];
__device__ float g_s1[BATCH*CH];
__device__ float g_s2[BATCH*CH];
__device__ float g_sr[BATCH*CH];
__device__ float g_d1[BATCH*CH];
__device__ float g_d2[BATCH*CH];

// ---------------------------------------------------------------------------
// PTX helpers (base-target features only: cp.async, ldmatrix, mma.sync)
// ---------------------------------------------------------------------------
__device__ __forceinline__ uint32_t smem_u32(const void* p) {
    uint32_t a;
    asm("{ .reg .u64 t; cvta.to.shared.u64 t, %1; cvt.u32.u64 %0, t; }"
        : "=r"(a) : "l"(p));
    return a;
}

__device__ __forceinline__ uint32_t pack_bf16x2(__nv_bfloat16 lo, __nv_bfloat16 hi) {
    return (uint32_t)__bfloat16_as_ushort(lo) | ((uint32_t)__bfloat16_as_ushort(hi) << 16);
}

#define CP_ASYNC16(dst, src) \
    asm volatile("cp.async.cg.shared.global [%0], [%1], 16;" \
        :: "r"(dst), "l"(src) : "memory")
#define CP_COMMIT() asm volatile("cp.async.commit_group;" ::: "memory")
#define CP_WAIT(N)  asm volatile("cp.async.wait_group %0;" :: "n"(N) : "memory")

__device__ __forceinline__ void ldsm_x4(uint32_t r[4], uint32_t addr) {
    asm volatile("ldmatrix.sync.aligned.m8n8.x4.shared.b16 {%0,%1,%2,%3}, [%4];"
        : "=r"(r[0]), "=r"(r[1]), "=r"(r[2]), "=r"(r[3]) : "r"(addr));
}

__device__ __forceinline__ void mma_bf16(float d[4], const uint32_t a[4],
                                         uint32_t b0, uint32_t b1) {
    asm volatile(
        "mma.sync.aligned.m16n8k16.row.col.f32.bf16.bf16.f32 "
        "{%0,%1,%2,%3}, {%4,%5,%6,%7}, {%8,%9}, {%0,%1,%2,%3};"
        : "+f"(d[0]), "+f"(d[1]), "+f"(d[2]), "+f"(d[3])
        : "r"(a[0]), "r"(a[1]), "r"(a[2]), "r"(a[3]), "r"(b0), "r"(b1));
}

// ---------------------------------------------------------------------------
// Launch 0: styles for all three mod layers. grid 48 x 256
// ---------------------------------------------------------------------------
__global__ void style_all_kernel(const float* __restrict__ w,
                                 const float* __restrict__ m1w, const float* __restrict__ m1b,
                                 const float* __restrict__ m2w, const float* __restrict__ m2b,
                                 const float* __restrict__ mrw, const float* __restrict__ mrb)
{
    int idx = blockIdx.x * 256 + threadIdx.x;    // 0 .. 3*4096
    if (idx >= 3 * BATCH * CH) return;
    int sel = idx >> 12;
    int r = idx & 4095;
    const float* mw = (sel == 0) ? m1w : (sel == 1) ? m2w : mrw;
    const float* mb = (sel == 0) ? m1b : (sel == 1) ? m2b : mrb;
    float* outp = (sel == 0) ? g_s1 : (sel == 1) ? g_s2 : g_sr;
    int b = r >> 9, c = r & 511;
    const float* wb = w + (size_t)b * CH;
    const float* mwc = mw + (size_t)c * CH;
    float acc = mb[c];
    #pragma unroll 8
    for (int t = 0; t < CH; t++) acc += wb[t] * mwc[t];
    outp[r] = acc;
}

// ---------------------------------------------------------------------------
// Launch 1: fused weight-pack + demod. grid (13312, 2), block 256.
//   blocks [0, 9216):  wpack — fp32 [co][ci][3][3] -> bf16 hi/lo [tap][co][ci]
//   blocks [9216, 13312): demod — d[b,co] = rsqrt(sum_ci wsq[co,ci]*s^2 + eps)
// ---------------------------------------------------------------------------
#define WPACK_BLOCKS 9216   // 512*512*9 / 256
__global__ void wpack_demod_kernel(const float* __restrict__ w1, const float* __restrict__ w2)
{
    const int which = blockIdx.y;
    const float* wgt = which ? w2 : w1;

    if (blockIdx.x < WPACK_BLOCKS) {
        int idx = blockIdx.x * 256 + threadIdx.x;
        __nv_bfloat16* out = which ? g_w2p : g_w1p;
        int ci = idx & 511, co = (idx >> 9) & 511, tap = idx >> 18;
        float v = wgt[((size_t)co * CH + ci) * 9 + tap];
        __nv_bfloat16 h = __float2bfloat16(v);
        out[(size_t)tap * (CH * CH) + (size_t)co * CH + ci] = h;
        out[(size_t)(9 + tap) * (CH * CH) + (size_t)co * CH + ci] =
            __float2bfloat16(v - __bfloat162float(h));
        return;
    }

    // demod part: one block per (b, co)
    __shared__ float red[256];
    const float* s = which ? g_s2 : g_s1;
    float* d       = which ? g_d2 : g_d1;
    const int bc = blockIdx.x - WPACK_BLOCKS;   // 0..4095
    const int b  = bc >> 9;
    const int co = bc & 511;
    const int t  = threadIdx.x;

    float partial = 0.f;
    #pragma unroll
    for (int h = 0; h < 2; h++) {
        int ci = t + h * 256;
        const float* p = wgt + ((size_t)co * CH + ci) * 9;
        float a = 0.f;
        #pragma unroll
        for (int tap = 0; tap < 9; tap++) a += p[tap] * p[tap];
        float sv = s[b * CH + ci];
        partial += a * sv * sv;
    }
    red[t] = partial;
    __syncthreads();
    for (int off = 128; off >= 32; off >>= 1) {
        if (t < off) red[t] += red[t + off];
        __syncthreads();
    }
    if (t < 32) {
        float v = red[t];
        #pragma unroll
        for (int off = 16; off > 0; off >>= 1)
            v += __shfl_down_sync(0xffffffffu, v, off);
        if (t == 0) d[b * CH + co] = rsqrtf(v + 1e-8f);
    }
}

// ---------------------------------------------------------------------------
// Launch 2: modulate(s1) + bilinear 2x upsample -> NHWC padded bf16 hi/lo,
// vectorized 32B stores; border zeroing in y==64 branch. grid (8,65,8) x 256
// ---------------------------------------------------------------------------
__global__ void upsample_pack_kernel(const float* __restrict__ x)
{
    __shared__ float rows[64][2][33];
    int b = blockIdx.z, y = blockIdx.y, c0 = blockIdx.x * 64;

    if (y == 64) {
        // border zero: 260 border pixels x 512 bf16 ch = 64 x uint4 per buffer
        for (int i = blockIdx.x * 256 + threadIdx.x; i < 260 * 64; i += 8 * 256) {
            int u = i & 63;
            int bp = i >> 6;
            int row, col;
            if (bp < 66)       { row = 0;  col = bp; }
            else if (bp < 132) { row = 65; col = bp - 66; }
            else { int j = bp - 132; row = 1 + (j >> 1); col = (j & 1) ? 65 : 0; }
            size_t off = (((size_t)(b * HP + row)) * WP + col) * CH;
            uint4 z = make_uint4(0, 0, 0, 0);
            ((uint4*)(g_a1h + off))[u] = z;
            ((uint4*)(g_a1l + off))[u] = z;
            ((uint4*)(g_a2h + off))[u] = z;
            ((uint4*)(g_a2l + off))[u] = z;
        }
        return;
    }

    float syf = y * 0.5f - 0.25f;
    int y0i = (int)floorf(syf);
    float fy = syf - (float)y0i;
    int ya = max(y0i, 0), yb = min(y0i + 1, HI - 1);
    for (int i = threadIdx.x; i < 64 * 2 * 32; i += 256) {
        int ci = i >> 6, r = (i >> 5) & 1, xx = i & 31;
        rows[ci][r][xx] = x[(((size_t)(b * CH + c0 + ci)) * HI + (r ? yb : ya)) * WI + xx];
    }
    __syncthreads();
    int px = threadIdx.x >> 2;
    int g  = (threadIdx.x & 3) * 16;
    float sxf = px * 0.5f - 0.25f;
    int x0i = (int)floorf(sxf);
    float fx = sxf - (float)x0i;
    int xa = max(x0i, 0), xb = min(x0i + 1, WI - 1);
    size_t obase = (((size_t)(b * HP + y + 1)) * WP + (px + 1)) * CH + c0 + g;

    uint32_t hbuf[8], lbuf[8];
    #pragma unroll
    for (int j2 = 0; j2 < 8; j2++) {
        float vv[2];
        #pragma unroll
        for (int e = 0; e < 2; e++) {
            int ci = g + j2 * 2 + e;
            float v0 = rows[ci][0][xa] * (1.f - fx) + rows[ci][0][xb] * fx;
            float v1 = rows[ci][1][xa] * (1.f - fx) + rows[ci][1][xb] * fx;
            vv[e] = (v0 * (1.f - fy) + v1 * fy) * g_s1[b * CH + c0 + ci];
        }
        __nv_bfloat16 h0 = __float2bfloat16(vv[0]);
        __nv_bfloat16 h1 = __float2bfloat16(vv[1]);
        __nv_bfloat16 l0 = __float2bfloat16(vv[0] - __bfloat162float(h0));
        __nv_bfloat16 l1 = __float2bfloat16(vv[1] - __bfloat162float(h1));
        hbuf[j2] = pack_bf16x2(h0, h1);
        lbuf[j2] = pack_bf16x2(l0, l1);
    }
    uint4* oh = (uint4*)(g_a1h + obase);
    uint4* ol = (uint4*)(g_a1l + obase);
    oh[0] = make_uint4(hbuf[0], hbuf[1], hbuf[2], hbuf[3]);
    oh[1] = make_uint4(hbuf[4], hbuf[5], hbuf[6], hbuf[7]);
    ol[0] = make_uint4(lbuf[0], lbuf[1], lbuf[2], lbuf[3]);
    ol[1] = make_uint4(lbuf[4], lbuf[5], lbuf[6], lbuf[7]);
}

// ---------------------------------------------------------------------------
// Launches 3,4: mma.sync implicit-GEMM conv3x3, bf16 hi/lo x3 split, fp32 acc.
// Block 256 thr (8 warps, 2M x 4N), tile M=128 px, N=256 co, BK=64, 2 stages.
// ---------------------------------------------------------------------------
#define STAGE 98304   // Ah 16K | Al 16K | Bh 32K | Bl 32K
#define DSMEM (2*STAGE)

template<int PHASE>
__global__ void __launch_bounds__(256, 1)
conv_mma_kernel(const __nv_bfloat16* __restrict__ aHi,
                const __nv_bfloat16* __restrict__ aLo,
                const __nv_bfloat16* __restrict__ wp,
                const float* __restrict__ dmod,
                const float* __restrict__ nscale,
                const float* __restrict__ noise,
                const float* __restrict__ s2,
                __nv_bfloat16* __restrict__ out_hi,
                __nv_bfloat16* __restrict__ out_lo,
                float* __restrict__ h_out)
{
    extern __shared__ __align__(128) char dsm[];
    __shared__ float e_d[256], e_ns[256], e_s2[256];

    const int tid = threadIdx.x;
    const int lane = tid & 31;
    const int wid = tid >> 5;
    const int warp_m = wid & 1;       // 2 x 64 pixels
    const int warp_n = wid >> 1;      // 4 x 64 couts
    const int co0 = blockIdx.x * 256;
    const int y0  = blockIdx.y * 2;   // 2 image rows = 128 pixels
    const int b   = blockIdx.z;

    const uint32_t sb = smem_u32(dsm);

    for (int i = tid; i < 256; i += 256) {
        e_d[i]  = dmod[b * CH + co0 + i];
        e_ns[i] = nscale[co0 + i];
        e_s2[i] = (PHASE == 1) ? s2[b * CH + co0 + i] : 0.f;
    }

    float acc[4][8][4] = {};

    auto issue = [&](int it, int buf) {
        const int tap = it >> 3;            // dy*3+dx
        const int ci0 = (it & 7) << 6;
        const int dy = tap / 3, dx = tap % 3;
        const uint32_t S = sb + buf * STAGE;
        #pragma unroll
        for (int rep = 0; rep < 8; rep++) {
            int i = tid + rep * 256;
            int op  = i >> 10;
            int c   = i & 1023;
            int row = c >> 3, col = c & 7;
            int py = y0 + (row >> 6) + dy;
            int px = (row & 63) + dx;
            const __nv_bfloat16* g = (op ? aLo : aHi)
                + ((((size_t)b * HP + py) * WP + px) << 9) + ci0 + (col << 3);
            uint32_t d = S + (op << 14) + row * 128 + ((col ^ (row & 7)) << 4);
            CP_ASYNC16(d, g);
        }
        #pragma unroll
        for (int rep = 0; rep < 16; rep++) {
            int i = tid + rep * 256;
            int op  = i >> 11;
            int c   = i & 2047;
            int row = c >> 3, col = c & 7;
            const __nv_bfloat16* g = wp
                + (((size_t)(op * 9 + tap) * CH + co0 + row) << 9) + ci0 + (col << 3);
            uint32_t d = S + 32768 + (op << 15) + row * 128 + ((col ^ (row & 7)) << 4);
            CP_ASYNC16(d, g);
        }
        CP_COMMIT();
    };

    issue(0, 0);

    #pragma unroll 1
    for (int it = 0; it < 72; ++it) {
        if (it + 1 < 72) { issue(it + 1, (it + 1) & 1); CP_WAIT(1); }
        else             { CP_WAIT(0); }
        __syncthreads();

        const uint32_t S = sb + (it & 1) * STAGE;

        #pragma unroll
        for (int ks = 0; ks < 4; ks++) {
            const int colA = ks * 2 + (lane >> 4);
            uint32_t ah[4][4], al[4][4], bh[4][4], bl[4][4];
            #pragma unroll
            for (int mt = 0; mt < 4; mt++) {
                int row = warp_m * 64 + mt * 16 + (lane & 15);
                uint32_t ad = S + row * 128 + ((colA ^ (row & 7)) << 4);
                ldsm_x4(ah[mt], ad);
                ldsm_x4(al[mt], ad + 16384);
            }
            #pragma unroll
            for (int nt = 0; nt < 4; nt++) {
                int row = warp_n * 64 + nt * 16 + (lane & 15);
                uint32_t bd = S + 32768 + row * 128 + ((colA ^ (row & 7)) << 4);
                ldsm_x4(bh[nt], bd);
                ldsm_x4(bl[nt], bd + 32768);
            }
            #pragma unroll
            for (int mt = 0; mt < 4; mt++)
                #pragma unroll
                for (int nt = 0; nt < 4; nt++)
                    #pragma unroll
                    for (int hf = 0; hf < 2; hf++) {
                        float* d = acc[mt][nt * 2 + hf];
                        uint32_t b0 = bh[nt][hf], b1 = bh[nt][hf + 2];
                        mma_bf16(d, ah[mt], b0, b1);                       // Ah*Bh
                        mma_bf16(d, al[mt], b0, b1);                       // Al*Bh
                        mma_bf16(d, ah[mt], bl[nt][hf], bl[nt][hf + 2]);   // Ah*Bl
                    }
        }
        __syncthreads();
    }

    // -------- epilogue --------
    #pragma unroll
    for (int mt = 0; mt < 4; mt++) {
        #pragma unroll
        for (int rr = 0; rr < 2; rr++) {
            int m = warp_m * 64 + mt * 16 + rr * 8 + (lane >> 2);
            int py = y0 + (m >> 6);
            int px = m & 63;
            float nz = noise[(size_t)b * PLANE_O + py * WO + px];
            #pragma unroll
            for (int nj = 0; nj < 8; nj++) {
                int nrel = warp_n * 64 + nj * 8 + (lane & 3) * 2;
                float v0 = acc[mt][nj][rr * 2 + 0] * e_d[nrel]     + e_ns[nrel]     * nz;
                float v1 = acc[mt][nj][rr * 2 + 1] * e_d[nrel + 1] + e_ns[nrel + 1] * nz;
                v0 = (v0 >= 0.f) ? v0 : 0.2f * v0;
                v1 = (v1 >= 0.f) ? v1 : 0.2f * v1;
                if (PHASE == 1) {
                    v0 *= e_s2[nrel];
                    v1 *= e_s2[nrel + 1];
                    __nv_bfloat16 h0 = __float2bfloat16(v0);
                    __nv_bfloat16 h1 = __float2bfloat16(v1);
                    __nv_bfloat16 l0 = __float2bfloat16(v0 - __bfloat162float(h0));
                    __nv_bfloat16 l1 = __float2bfloat16(v1 - __bfloat162float(h1));
                    size_t o = ((((size_t)b * HP + py + 1) * WP) + px + 1) * CH + co0 + nrel;
                    *(uint32_t*)(out_hi + o) = pack_bf16x2(h0, h1);
                    *(uint32_t*)(out_lo + o) = pack_bf16x2(l0, l1);
                } else {
                    size_t o = ((size_t)b * CH + co0 + nrel) * PLANE_O + py * WO + px;
                    h_out[o] = v0;
                    h_out[o + PLANE_O] = v1;
                }
            }
        }
    }
}

// ---------------------------------------------------------------------------
// Launch 5: to-RGB 1x1 conv
// ---------------------------------------------------------------------------
__global__ void rgb_kernel(const float* __restrict__ h, const float* __restrict__ rgbw,
                           float* __restrict__ rgb)
{
    __shared__ float weff[3 * CH];
    int b = blockIdx.y;
    for (int i = threadIdx.x; i < 3 * CH; i += 256) {
        int c = i / CH, ci = i % CH;
        weff[i] = rgbw[c * CH + ci] * g_sr[b * CH + ci];
    }
    __syncthreads();
    int pix = blockIdx.x * 256 + threadIdx.x;
    const float* hb = h + (size_t)b * CH * PLANE_O + pix;
    float a0 = 0.f, a1 = 0.f, a2 = 0.f;
    #pragma unroll 4
    for (int ci = 0; ci < CH; ci++) {
        float hv = hb[(size_t)ci * PLANE_O];
        a0 += weff[ci] * hv;
        a1 += weff[CH + ci] * hv;
        a2 += weff[2 * CH + ci] * hv;
    }
    float* rb = rgb + (size_t)b * 3 * PLANE_O + pix;
    rb[0] = a0; rb[PLANE_O] = a1; rb[2 * PLANE_O] = a2;
}

// ---------------------------------------------------------------------------
// host launch
// ---------------------------------------------------------------------------
extern "C" void kernel_launch(void* const* d_in, const int* in_sizes, int n_in,
                              void* d_out, int out_size)
{
    const float* x   = (const float*)d_in[0];
    const float* w   = (const float*)d_in[1];
    const float* w1  = (const float*)d_in[2];
    const float* m1w = (const float*)d_in[3];
    const float* m1b = (const float*)d_in[4];
    const float* ns1 = (const float*)d_in[5];
    const float* w2  = (const float*)d_in[6];
    const float* m2w = (const float*)d_in[7];
    const float* m2b = (const float*)d_in[8];
    const float* ns2 = (const float*)d_in[9];
    const float* wr  = (const float*)d_in[10];
    const float* mrw = (const float*)d_in[11];
    const float* mrb = (const float*)d_in[12];
    const float* n1  = (const float*)d_in[13];
    const float* n2  = (const float*)d_in[14];

    float* out     = (float*)d_out;
    float* h_out   = out;                                  // [8,512,64,64]
    float* rgb_out = out + (size_t)BATCH * CH * PLANE_O;   // [8,3,64,64]

    float *p_s2, *p_d1, *p_d2;
    __nv_bfloat16 *p_a1h, *p_a1l, *p_a2h, *p_a2l, *p_w1p, *p_w2p;
    cudaGetSymbolAddress((void**)&p_s2, g_s2);
    cudaGetSymbolAddress((void**)&p_d1, g_d1);
    cudaGetSymbolAddress((void**)&p_d2, g_d2);
    cudaGetSymbolAddress((void**)&p_a1h, g_a1h);
    cudaGetSymbolAddress((void**)&p_a1l, g_a1l);
    cudaGetSymbolAddress((void**)&p_a2h, g_a2h);
    cudaGetSymbolAddress((void**)&p_a2l, g_a2l);
    cudaGetSymbolAddress((void**)&p_w1p, g_w1p);
    cudaGetSymbolAddress((void**)&p_w2p, g_w2p);

    cudaFuncSetAttribute(conv_mma_kernel<1>, cudaFuncAttributeMaxDynamicSharedMemorySize, DSMEM);
    cudaFuncSetAttribute(conv_mma_kernel<2>, cudaFuncAttributeMaxDynamicSharedMemorySize, DSMEM);

    // 0. styles
    style_all_kernel<<<48, 256>>>(w, m1w, m1b, m2w, m2b, mrw, mrb);
    // 1. fused weight-pack + demod (both convs)
    wpack_demod_kernel<<<dim3(WPACK_BLOCKS + BATCH * CH, 2), 256>>>(w1, w2);
    // 2. modulate + upsample + border zero
    {
        dim3 g(8, 65, 8);
        upsample_pack_kernel<<<g, 256>>>(x);
    }
    // 3. conv1 (reads a1 hi/lo, writes conv2 input a2 hi/lo, pre-modulated by s2)
    {
        dim3 g(2, 32, 8);
        conv_mma_kernel<1><<<g, 256, DSMEM>>>(p_a1h, p_a1l, p_w1p, p_d1, ns1, n1,
                                              p_s2, p_a2h, p_a2l, nullptr);
    }
    // 4. conv2 (reads a2 hi/lo, writes h_out fp32)
    {
        dim3 g(2, 32, 8);
        conv_mma_kernel<2><<<g, 256, DSMEM>>>(p_a2h, p_a2l, p_w2p, p_d2, ns2, n2,
                                              nullptr, nullptr, nullptr, h_out);
    }
    // 5. rgb
    {
        dim3 g(PLANE_O / 256, BATCH);
        rgb_kernel<<<g, 256>>>(h_out, wr, rgb_out);
    }
    (void)in_sizes; (void)n_in; (void)out_size;
}